// round 4
// baseline (speedup 1.0000x reference)
#include <cuda_runtime.h>
#include <cuda_bf16.h>
#include <cstdint>

// ---------------- problem constants ----------------
#define D_IN    1024
#define M_HID   4096
#define BATCH   16384
#define R_LORA  16
#define LSCALE  2.0f

// ---------------- GEMM tiling ----------------
#define BM      128                 // batch rows per CTA
#define BN      128                 // hidden cols per CTA
#define KITERS  32                  // 32 iters x (32 bf16 k / 64 fp8 bytes)
#define NT      (M_HID / BN)        // 32
#define MT      (BATCH / BM)        // 128
#define NTHREADS 256

// smem: 4 tensors per stage, each 128 rows x 64B payload, 80B stride
#define ROWB    80
#define TILEB   (BM * ROWB)          // 10240
#define STAGEB  (4 * TILEB)          // 40960
#define NSTAGE  3
#define BIAS_OFF (NSTAGE * STAGEB)   // 122880
#define W2_OFF   (BIAS_OFF + BN * 4)
#define RED_OFF  (W2_OFF + BN * 4)
#define SMEM_TOTAL (RED_OFF + BM * 2 * 4)   // 124928

// correction product scale = 2^13 (x_lo*2^9 * w_hi*2^4, x_hi*2^4 * w_lo*2^9)
#define INV_CORR (1.0f / 8192.0f)

// ---------------- scratch (static device globals) ----------------
__device__ __align__(1024) __nv_bfloat16 g_xhi[BATCH * D_IN];      // 32 MB
__device__ __align__(1024) uint8_t       g_x8 [BATCH * 2 * D_IN];  // 32 MB [lo*2^9 | hi*2^4]
__device__ __align__(1024) __nv_bfloat16 g_whi[M_HID * D_IN];      //  8 MB
__device__ __align__(1024) uint8_t       g_w8 [M_HID * 2 * D_IN];  //  8 MB [hi*2^4 | lo*2^9]
__device__ float g_partial[NT * BATCH];                            //  2 MB

// ---------------- PTX helpers ----------------
__device__ __forceinline__ uint32_t smem_u32(const void* p) {
    uint32_t a;
    asm("{ .reg .u64 t; cvta.to.shared.u64 t, %1; cvt.u32.u64 %0, t; }"
        : "=r"(a) : "l"(p));
    return a;
}

#define CP_ASYNC16(s, g) \
    asm volatile("cp.async.cg.shared.global [%0], [%1], 16;" :: "r"(s), "l"(g) : "memory")
#define CP_COMMIT() asm volatile("cp.async.commit_group;" ::: "memory")
#define CP_WAIT(n)  asm volatile("cp.async.wait_group %0;" :: "n"(n) : "memory")

__device__ __forceinline__ void ldsm4(uint32_t* r, uint32_t addr) {
    asm volatile("ldmatrix.sync.aligned.m8n8.x4.shared.b16 {%0,%1,%2,%3}, [%4];"
                 : "=r"(r[0]), "=r"(r[1]), "=r"(r[2]), "=r"(r[3]) : "r"(addr));
}

__device__ __forceinline__ void mma_bf16(float* c, const uint32_t* a, const uint32_t* b) {
    asm volatile(
        "mma.sync.aligned.m16n8k16.row.col.f32.bf16.bf16.f32 "
        "{%0,%1,%2,%3}, {%4,%5,%6,%7}, {%8,%9}, {%0,%1,%2,%3};"
        : "+f"(c[0]), "+f"(c[1]), "+f"(c[2]), "+f"(c[3])
        : "r"(a[0]), "r"(a[1]), "r"(a[2]), "r"(a[3]), "r"(b[0]), "r"(b[1]));
}

__device__ __forceinline__ void mma_fp8(float* c, const uint32_t* a, const uint32_t* b) {
    asm volatile(
        "mma.sync.aligned.m16n8k32.row.col.f32.e4m3.e4m3.f32 "
        "{%0,%1,%2,%3}, {%4,%5,%6,%7}, {%8,%9}, {%0,%1,%2,%3};"
        : "+f"(c[0]), "+f"(c[1]), "+f"(c[2]), "+f"(c[3])
        : "r"(a[0]), "r"(a[1]), "r"(a[2]), "r"(a[3]), "r"(b[0]), "r"(b[1]));
}

__device__ __forceinline__ uint32_t pack_bf2(float a, float b) {
    __nv_bfloat162 t = __floats2bfloat162_rn(a, b);
    return *(uint32_t*)&t;
}

// pack 4 floats into 4 e4m3 bytes (saturating)
__device__ __forceinline__ uint32_t pack_e4m3x4(float f0, float f1, float f2, float f3) {
    uint32_t r;
    asm("{ .reg .b16 lo, hi;\n\t"
        "cvt.rn.satfinite.e4m3x2.f32 lo, %2, %1;\n\t"
        "cvt.rn.satfinite.e4m3x2.f32 hi, %4, %3;\n\t"
        "mov.b32 %0, {lo, hi}; }"
        : "=r"(r) : "f"(f0), "f"(f1), "f"(f2), "f"(f3));
    return r;
}

// ==================================================================
// Kernel A: split x -> bf16 hi + fp8 [lo*512 | hi*16]
// each thread handles 8 consecutive floats
// ==================================================================
__global__ __launch_bounds__(256) void split_x_kernel(const float* __restrict__ x) {
    size_t i = ((size_t)blockIdx.x * 256 + threadIdx.x);
    size_t base = i * 8;
    float4 v0 = ((const float4*)x)[i * 2];
    float4 v1 = ((const float4*)x)[i * 2 + 1];
    float f[8] = {v0.x, v0.y, v0.z, v0.w, v1.x, v1.y, v1.z, v1.w};
    float h[8], l[8];
#pragma unroll
    for (int j = 0; j < 8; ++j) {
        h[j] = __bfloat162float(__float2bfloat16(f[j]));
        l[j] = f[j] - h[j];
    }
    uint4 bh;
    bh.x = pack_bf2(h[0], h[1]); bh.y = pack_bf2(h[2], h[3]);
    bh.z = pack_bf2(h[4], h[5]); bh.w = pack_bf2(h[6], h[7]);
    *(uint4*)(g_xhi + base) = bh;

    size_t row = base >> 10, col = base & 1023;
    uint2 lo8, hi8;
    lo8.x = pack_e4m3x4(l[0] * 512.f, l[1] * 512.f, l[2] * 512.f, l[3] * 512.f);
    lo8.y = pack_e4m3x4(l[4] * 512.f, l[5] * 512.f, l[6] * 512.f, l[7] * 512.f);
    hi8.x = pack_e4m3x4(h[0] * 16.f, h[1] * 16.f, h[2] * 16.f, h[3] * 16.f);
    hi8.y = pack_e4m3x4(h[4] * 16.f, h[5] * 16.f, h[6] * 16.f, h[7] * 16.f);
    *(uint2*)(g_x8 + row * 2048 + col)        = lo8;
    *(uint2*)(g_x8 + row * 2048 + 1024 + col) = hi8;
}

// ==================================================================
// Kernel B: W_eff = W0 + 2*(B@A) -> bf16 hi + fp8 [hi*16 | lo*512]
// ==================================================================
__global__ __launch_bounds__(256) void weff_split_kernel(
    const float* __restrict__ W0, const float* __restrict__ A,
    const float* __restrict__ Bm)
{
    int m = blockIdx.x;
    float br[R_LORA];
#pragma unroll
    for (int r = 0; r < R_LORA; ++r) br[r] = Bm[m * R_LORA + r] * LSCALE;

    int d4 = threadIdx.x;   // 0..255, 4 floats each
    float4 acc = ((const float4*)(W0 + (size_t)m * D_IN))[d4];
#pragma unroll
    for (int r = 0; r < R_LORA; ++r) {
        float4 a = ((const float4*)(A + (size_t)r * D_IN))[d4];
        acc.x = fmaf(br[r], a.x, acc.x);
        acc.y = fmaf(br[r], a.y, acc.y);
        acc.z = fmaf(br[r], a.z, acc.z);
        acc.w = fmaf(br[r], a.w, acc.w);
    }
    float f[4] = {acc.x, acc.y, acc.z, acc.w};
    float h[4], l[4];
#pragma unroll
    for (int j = 0; j < 4; ++j) {
        h[j] = __bfloat162float(__float2bfloat16(f[j]));
        l[j] = f[j] - h[j];
    }
    uint2 bh;
    bh.x = pack_bf2(h[0], h[1]); bh.y = pack_bf2(h[2], h[3]);
    *(uint2*)(g_whi + (size_t)m * D_IN + d4 * 4) = bh;

    uint32_t hi8 = pack_e4m3x4(h[0] * 16.f, h[1] * 16.f, h[2] * 16.f, h[3] * 16.f);
    uint32_t lo8 = pack_e4m3x4(l[0] * 512.f, l[1] * 512.f, l[2] * 512.f, l[3] * 512.f);
    *(uint32_t*)(g_w8 + (size_t)m * 2048 + d4 * 4)        = hi8;
    *(uint32_t*)(g_w8 + (size_t)m * 2048 + 1024 + d4 * 4) = lo8;
}

// ==================================================================
// Kernel C: bf16 hi GEMM + fp8 concat-K correction GEMM + relu-dot epi
// grid (NT=32, MT=128), 256 threads (8 warps: 4 along M x 2 along N)
// warp tile 32x64; two fp32 accumulator sets (64 + 64 regs)
// ==================================================================
__device__ __forceinline__ void issue_stage(uint32_t sst, int kit, int b0, int n0, int tid)
{
#pragma unroll
    for (int i = 0; i < 2; ++i) {
        int idx = tid + i * 256;
        int r = idx >> 2, c = idx & 3;
        uint32_t soff = (uint32_t)(r * ROWB + c * 16);
        CP_ASYNC16(sst + soff,
                   g_xhi + (size_t)(b0 + r) * D_IN + kit * 32 + c * 8);
        CP_ASYNC16(sst + TILEB + soff,
                   g_x8 + (size_t)(b0 + r) * 2048 + kit * 64 + c * 16);
        CP_ASYNC16(sst + 2 * TILEB + soff,
                   g_whi + (size_t)(n0 + r) * D_IN + kit * 32 + c * 8);
        CP_ASYNC16(sst + 3 * TILEB + soff,
                   g_w8 + (size_t)(n0 + r) * 2048 + kit * 64 + c * 16);
    }
}

__global__ void __launch_bounds__(NTHREADS, 1) main_mma_kernel(
    const float* __restrict__ b0v, const float* __restrict__ W2)
{
    extern __shared__ __align__(128) char smem[];
    const uint32_t sb = smem_u32(smem);
    const int tid  = threadIdx.x;
    const int wid  = tid >> 5;
    const int lane = tid & 31;
    const int wm   = wid >> 1;           // 0..3  (32-row slice)
    const int wn   = wid & 1;            // 0..1  (64-col slice)
    const int n0   = blockIdx.x * BN;
    const int b0   = blockIdx.y * BM;

    if (tid < BN) {
        ((float*)(smem + BIAS_OFF))[tid] = b0v[n0 + tid];
        ((float*)(smem + W2_OFF))[tid]   = W2[n0 + tid];
    }

    float abf[2][8][4], af8[2][8][4];
#pragma unroll
    for (int mt = 0; mt < 2; ++mt)
#pragma unroll
        for (int nt = 0; nt < 8; ++nt)
#pragma unroll
            for (int e = 0; e < 4; ++e) { abf[mt][nt][e] = 0.f; af8[mt][nt][e] = 0.f; }

    const uint32_t aoff = (uint32_t)((lane & 15) * ROWB + (lane >> 4) * 16);
    const uint32_t boff = (uint32_t)((((lane & 7) + ((lane >> 4) << 3)) * ROWB)
                                     + ((lane >> 3) & 1) * 16);

    issue_stage(sb, 0, b0, n0, tid); CP_COMMIT();
    issue_stage(sb + STAGEB, 1, b0, n0, tid); CP_COMMIT();

    for (int it = 0; it < KITERS; ++it) {
        if (it + 2 < KITERS) { CP_WAIT(1); } else { CP_WAIT(0); }
        __syncthreads();
        if (it + 2 < KITERS) {
            uint32_t nst = sb + (uint32_t)(((it + 2) % NSTAGE) * STAGEB);
            issue_stage(nst, it + 2, b0, n0, tid);
            CP_COMMIT();
        }
        const uint32_t st = sb + (uint32_t)((it % NSTAGE) * STAGEB);

        // ---- bf16 hi*hi : 2 k16 slices ----
#pragma unroll
        for (int ks = 0; ks < 2; ++ks) {
            const uint32_t kb = (uint32_t)(ks * 32);
            uint32_t a[2][4], b[4][4];
#pragma unroll
            for (int mt = 0; mt < 2; ++mt)
                ldsm4(a[mt], st + (uint32_t)((wm * 32 + mt * 16) * ROWB) + kb + aoff);
#pragma unroll
            for (int bt = 0; bt < 4; ++bt)
                ldsm4(b[bt], st + 2 * TILEB
                             + (uint32_t)((wn * 64 + bt * 16) * ROWB) + kb + boff);
#pragma unroll
            for (int mt = 0; mt < 2; ++mt)
#pragma unroll
                for (int nt = 0; nt < 8; ++nt)
                    mma_bf16(abf[mt][nt], a[mt], &b[nt >> 1][(nt & 1) * 2]);
        }

        // ---- fp8 correction (concat-K) : 2 k32 slices ----
#pragma unroll
        for (int ks = 0; ks < 2; ++ks) {
            const uint32_t kb = (uint32_t)(ks * 32);
            uint32_t a[2][4], b[4][4];
#pragma unroll
            for (int mt = 0; mt < 2; ++mt)
                ldsm4(a[mt], st + TILEB
                             + (uint32_t)((wm * 32 + mt * 16) * ROWB) + kb + aoff);
#pragma unroll
            for (int bt = 0; bt < 4; ++bt)
                ldsm4(b[bt], st + 3 * TILEB
                             + (uint32_t)((wn * 64 + bt * 16) * ROWB) + kb + boff);
#pragma unroll
            for (int mt = 0; mt < 2; ++mt)
#pragma unroll
                for (int nt = 0; nt < 8; ++nt)
                    mma_fp8(af8[mt][nt], a[mt], &b[nt >> 1][(nt & 1) * 2]);
        }
    }

    // ---- epilogue: relu(h_hi + corr/8192 + bias) . W2 ----
    const float* bias = (const float*)(smem + BIAS_OFF);
    const float* w2s  = (const float*)(smem + W2_OFF);
    float* red        = (float*)(smem + RED_OFF);   // [BM][2]

    __syncthreads();
#pragma unroll
    for (int mt = 0; mt < 2; ++mt) {
#pragma unroll
        for (int hh = 0; hh < 2; ++hh) {
            float s = 0.f;
#pragma unroll
            for (int nt = 0; nt < 8; ++nt) {
#pragma unroll
                for (int e = 0; e < 2; ++e) {
                    int col = wn * 64 + nt * 8 + (lane & 3) * 2 + e;
                    float hv = abf[mt][nt][hh * 2 + e]
                             + af8[mt][nt][hh * 2 + e] * INV_CORR
                             + bias[col];
                    s = fmaf(fmaxf(hv, 0.f), w2s[col], s);
                }
            }
            s += __shfl_xor_sync(0xffffffffu, s, 1);
            s += __shfl_xor_sync(0xffffffffu, s, 2);
            if ((lane & 3) == 0) {
                int row = wm * 32 + mt * 16 + (lane >> 2) + hh * 8;
                red[row * 2 + wn] = s;
            }
        }
    }
    __syncthreads();

    if (tid < BM) {
        float s = red[tid * 2] + red[tid * 2 + 1];
        g_partial[(size_t)blockIdx.x * BATCH + b0 + tid] = s;
    }
}

// ==================================================================
// Kernel D: out[b] = b2 + sum_nt partial[nt][b]
// ==================================================================
__global__ __launch_bounds__(256) void finalize_kernel(
    const float* __restrict__ b2, float* __restrict__ out)
{
    int b = blockIdx.x * 256 + threadIdx.x;
    float s = b2[0];
#pragma unroll
    for (int t = 0; t < NT; ++t)
        s += g_partial[(size_t)t * BATCH + b];
    out[b] = s;
}

// ==================================================================
extern "C" void kernel_launch(void* const* d_in, const int* in_sizes, int n_in,
                              void* d_out, int out_size)
{
    const float* x   = (const float*)d_in[0];
    const float* W0  = (const float*)d_in[1];
    const float* b0v = (const float*)d_in[2];
    const float* A   = (const float*)d_in[3];
    const float* Bm  = (const float*)d_in[4];
    const float* W2  = (const float*)d_in[5];
    const float* b2  = (const float*)d_in[6];
    float* out = (float*)d_out;

    cudaFuncSetAttribute(main_mma_kernel,
                         cudaFuncAttributeMaxDynamicSharedMemorySize, SMEM_TOTAL);

    split_x_kernel<<<(BATCH * D_IN) / (256 * 8), 256>>>(x);
    weff_split_kernel<<<M_HID, 256>>>(W0, A, Bm);

    dim3 grid(NT, MT);
    main_mma_kernel<<<grid, NTHREADS, SMEM_TOTAL>>>(b0v, W2);

    finalize_kernel<<<BATCH / 256, 256>>>(b2, out);
}